// round 1
// baseline (speedup 1.0000x reference)
#include <cuda_runtime.h>
#include <cuda_bf16.h>

// FWHT over rows of length 4096: H4096 = H2^{⊗12}.
// 3 register-resident H16 rounds (4 bits each) + 2 smem exchanges.
// Bit partition per round:
//   round 1: bits {0,1,10,11}  (falls out of the coalesced float4 load layout)
//   round 2: bits {2,3,4,5}
//   round 3: bits {6,7,8,9}
// XOR swizzle keeps all smem access patterns 32-bank conflict-free.

#define FWHT_N 4096
#define FWHT_THREADS 256

__device__ __forceinline__ int fwht_swz(int i) {
    // XOR bits {6,7,8} into bits {2,3,4}. Preserves float4 alignment
    // (bits 0..1 untouched; source bits constant within a float4).
    return i ^ (((i >> 6) & 7) << 2);
}

__device__ __forceinline__ void fwht_h16(float* v) {
#pragma unroll
    for (int h = 1; h < 16; h <<= 1) {
#pragma unroll
        for (int s = 0; s < 16; s += 2 * h) {
#pragma unroll
            for (int k = 0; k < h; k++) {
                float a = v[s + k];
                float b = v[s + k + h];
                v[s + k]     = a + b;
                v[s + k + h] = a - b;
            }
        }
    }
}

__global__ void __launch_bounds__(FWHT_THREADS)
fwht4096_kernel(const float* __restrict__ x,
                const float* __restrict__ scale,
                float* __restrict__ out)
{
    __shared__ float S[FWHT_N];

    const int row = blockIdx.x;
    const int t   = threadIdx.x;

    const float4* xr = reinterpret_cast<const float4*>(x) + (size_t)row * (FWHT_N / 4);

    float v[16];

    // ---- load (fully coalesced float4) ----
    // v[4j+k] = x[row, 1024*j + 4*t + k]
#pragma unroll
    for (int j = 0; j < 4; j++) {
        float4 f = xr[256 * j + t];
        v[4 * j + 0] = f.x;
        v[4 * j + 1] = f.y;
        v[4 * j + 2] = f.z;
        v[4 * j + 3] = f.w;
    }

    // ---- round 1: butterflies over bits {0,1,10,11} (register-resident) ----
    fwht_h16(v);

    // store to smem as swizzled float4 (conflict-free)
#pragma unroll
    for (int j = 0; j < 4; j++) {
        int i = 1024 * j + 4 * t;        // bits 0..1 are zero -> float4 aligned
        int p = fwht_swz(i);             // still float4 aligned
        *reinterpret_cast<float4*>(&S[p]) =
            make_float4(v[4 * j + 0], v[4 * j + 1], v[4 * j + 2], v[4 * j + 3]);
    }
    __syncthreads();

    // ---- round 2: butterflies over bits {2,3,4,5} ----
    // thread owns: bits{0,1} = t&3, bits{6..8} = (t>>2)&7, bits{9..11} = t>>5
    {
        const int base = (t & 3) | (((t >> 2) & 7) << 6) | ((t >> 5) << 9);
#pragma unroll
        for (int m = 0; m < 16; m++)
            v[m] = S[fwht_swz(base | (m << 2))];

        fwht_h16(v);

#pragma unroll
        for (int m = 0; m < 16; m++)
            S[fwht_swz(base | (m << 2))] = v[m];
    }
    __syncthreads();

    // ---- round 3: butterflies over bits {6,7,8,9} ----
    // thread owns: bits{0..5} = t&63, bits{10,11} = t>>6
    {
        const int base = (t & 63) | ((t >> 6) << 10);
#pragma unroll
        for (int m = 0; m < 16; m++)
            v[m] = S[fwht_swz(base | (m << 6))];

        fwht_h16(v);

        const float sc = *scale;
        float* orow = out + (size_t)row * FWHT_N;
        // for fixed m, lanes cover 32 consecutive floats -> 128B coalesced stores
#pragma unroll
        for (int m = 0; m < 16; m++)
            orow[base | (m << 6)] = v[m] * sc;
    }
}

extern "C" void kernel_launch(void* const* d_in, const int* in_sizes, int n_in,
                              void* d_out, int out_size)
{
    const float* x     = (const float*)d_in[0];
    const float* scale = (const float*)d_in[1];
    float* out         = (float*)d_out;

    const int rows = in_sizes[0] / FWHT_N;

    fwht4096_kernel<<<rows, FWHT_THREADS>>>(x, scale, out);
}